// round 14
// baseline (speedup 1.0000x reference)
#include <cuda_runtime.h>
#include <cuda_bf16.h>
#include <stdint.h>
#include <math.h>

// Problem constants
#define B_ANCH 2048
#define P_POS  4
#define D_DIM  256
#define NNEG   32768
#define INV_T  20.0f
#define ALPHA_W 0.1f
#define EPS_N  1e-12f
#define LOG2E20 28.853900817779268f          // 20 * log2(e)
#define QSCALE  (LOG2E20 / 16129.0f)         // 20*log2(e) / 127^2

// Tiling (int8: rows are 256 B)
#define MT     128
#define NT     128
#define NSPLIT 64
#define CHUNK  (NNEG / NSPLIT)   // 512
#define SUBT   (CHUNK / NT)      // 4
#define TILE_BYTES (MT * D_DIM)          // 32 KB
#define SMEM_TOTAL (3 * TILE_BYTES)      // 96 KB -> 2 CTAs/SM

// ---------------- scratch ----------------
__device__ __align__(16) int8_t g_an_q[B_ANCH * D_DIM];
__device__ __align__(16) int8_t g_nn_q[NNEG * D_DIM];
__device__ float g_pos[B_ANCH * P_POS];
__device__ float g_ps[NSPLIT * B_ANCH];

// ---------------- helpers ----------------
__device__ __forceinline__ uint32_t smem_u32(const void* p) {
    uint32_t a;
    asm("{ .reg .u64 t; cvta.to.shared.u64 t, %1; cvt.u32.u64 %0, t; }" : "=r"(a) : "l"(p));
    return a;
}
__device__ __forceinline__ void ldsm_x4(uint32_t* r, uint32_t addr) {
    asm volatile("ldmatrix.sync.aligned.m8n8.x4.shared.b16 {%0,%1,%2,%3}, [%4];"
                 : "=r"(r[0]), "=r"(r[1]), "=r"(r[2]), "=r"(r[3]) : "r"(addr));
}
__device__ __forceinline__ void mma_s8(int* d, const uint32_t* a, const uint32_t* b) {
    asm volatile("mma.sync.aligned.m16n8k32.row.col.s32.s8.s8.s32 "
                 "{%0,%1,%2,%3}, {%4,%5,%6,%7}, {%8,%9}, {%0,%1,%2,%3};"
                 : "+r"(d[0]), "+r"(d[1]), "+r"(d[2]), "+r"(d[3])
                 : "r"(a[0]), "r"(a[1]), "r"(a[2]), "r"(a[3]), "r"(b[0]), "r"(b[1]));
}
__device__ __forceinline__ float ex2f(float x) {
    float y;
    asm("ex2.approx.ftz.f32 %0, %1;" : "=f"(y) : "f"(x));
    return y;
}
__device__ __forceinline__ float logaddexpf_(float a, float b) {
    float hi = fmaxf(a, b), lo = fminf(a, b);
    return hi + log1pf(expf(lo - hi));
}
// quantize 4 floats (already normalized) by s, pack to s8x4
__device__ __forceinline__ uint32_t q4(float4 v, float s) {
    int a = __float2int_rn(v.x * s);
    int b = __float2int_rn(v.y * s);
    int c = __float2int_rn(v.z * s);
    int d = __float2int_rn(v.w * s);
    a = max(-127, min(127, a)); b = max(-127, min(127, b));
    c = max(-127, min(127, c)); d = max(-127, min(127, d));
    return (uint32_t)(a & 0xff) | ((uint32_t)(b & 0xff) << 8) |
           ((uint32_t)(c & 0xff) << 16) | ((uint32_t)(d & 0xff) << 24);
}

// 128 rows x 256 B tile fill. 16B chunks (16/row), XOR swizzle chunk' = chunk ^ (row&7)
__device__ __forceinline__ void cp_fill(uint32_t dstBase, const int8_t* src, int tid) {
#pragma unroll
    for (int i = 0; i < 8; ++i) {
        int idx = tid + (i << 8);       // 0..2047
        int r = idx >> 4;               // row 0..127
        int c = idx & 15;               // chunk 0..15
        uint32_t dst = dstBase + r * 256 + (uint32_t)((c ^ (r & 7)) << 4);
        const void* g = (const void*)(src + (size_t)r * D_DIM + c * 16);
        asm volatile("cp.async.cg.shared.global [%0], [%1], 16;" :: "r"(dst), "l"(g) : "memory");
    }
}

// ---------------------------------------------------------------------------
// Fused prologue (warp per unit): anchor-quant / negative-quant / pos_sim
// ---------------------------------------------------------------------------
#define U_ANC  B_ANCH
#define U_NEG  (U_ANC + NNEG)
#define U_TOT  (U_NEG + B_ANCH * P_POS)

__global__ void prologue_kernel(const float* __restrict__ anc,
                                const float* __restrict__ pos,
                                const float* __restrict__ neg) {
    int u = (blockIdx.x * blockDim.x + threadIdx.x) >> 5;
    int lane = threadIdx.x & 31;
    if (u >= U_TOT) return;

    if (u < U_NEG) {
        const float* src;
        int8_t* dst;
        if (u < U_ANC) { src = anc + (size_t)u * D_DIM;           dst = g_an_q + (size_t)u * D_DIM; }
        else           { src = neg + (size_t)(u - U_ANC) * D_DIM; dst = g_nn_q + (size_t)(u - U_ANC) * D_DIM; }
        const float4* s4 = (const float4*)src;
        float4 v0 = s4[lane];
        float4 v1 = s4[lane + 32];
        float ss = v0.x*v0.x + v0.y*v0.y + v0.z*v0.z + v0.w*v0.w
                 + v1.x*v1.x + v1.y*v1.y + v1.z*v1.z + v1.w*v1.w;
#pragma unroll
        for (int o = 16; o > 0; o >>= 1) ss += __shfl_xor_sync(0xffffffffu, ss, o);
        float s = 127.0f / fmaxf(sqrtf(ss), EPS_N);
        uint32_t* d32 = (uint32_t*)dst;
        d32[lane]      = q4(v0, s);
        d32[lane + 32] = q4(v1, s);
    } else {
        int p = u - U_NEG;
        int b = p >> 2;
        const float4* psrc = (const float4*)(pos + (size_t)p * D_DIM);
        const float4* asrc = (const float4*)(anc + (size_t)b * D_DIM);
        float sp = 0.f, sa = 0.f, dot = 0.f;
#pragma unroll
        for (int t = 0; t < 2; ++t) {
            float4 pv = psrc[lane + 32 * t];
            float4 av = asrc[lane + 32 * t];
            sp  += pv.x*pv.x + pv.y*pv.y + pv.z*pv.z + pv.w*pv.w;
            sa  += av.x*av.x + av.y*av.y + av.z*av.z + av.w*av.w;
            dot += pv.x*av.x + pv.y*av.y + pv.z*av.z + pv.w*av.w;
        }
#pragma unroll
        for (int o = 16; o > 0; o >>= 1) {
            sp  += __shfl_xor_sync(0xffffffffu, sp, o);
            sa  += __shfl_xor_sync(0xffffffffu, sa, o);
            dot += __shfl_xor_sync(0xffffffffu, dot, o);
        }
        if (lane == 0)
            g_pos[p] = dot / (fmaxf(sqrtf(sp), EPS_N) * fmaxf(sqrtf(sa), EPS_N)) * INV_T;
    }
}

// ---------------------------------------------------------------------------
// Main: int8 warp-MMA GEMM + exp partial-sum. grid (16, NSPLIT), 256 thr,
// 8 warps (2x4), warp tile 64x32, K=256 in 8 k32 steps. 2 CTAs/SM.
// ---------------------------------------------------------------------------
__global__ void __launch_bounds__(256, 2) neg_mma_kernel() {
    extern __shared__ char smem[];
    __shared__ float wsum[4][MT];

    const uint32_t Abase = smem_u32(smem);
    const uint32_t Bb[2] = { Abase + TILE_BYTES, Abase + 2 * TILE_BYTES };

    int tid = threadIdx.x;
    int l = tid & 31;
    int wid = tid >> 5;
    int warp_m = wid >> 2;
    int warp_n = wid & 3;
    int aBase = blockIdx.x * MT;
    int nBase = blockIdx.y * CHUNK;

    const int8_t* Ag = g_an_q + (size_t)aBase * D_DIM;
    const int8_t* Bg = g_nn_q + (size_t)nBase * D_DIM;

    cp_fill(Abase, Ag, tid);
    cp_fill(Bb[0], Bg, tid);
    asm volatile("cp.async.commit_group;" ::: "memory");
    asm volatile("cp.async.wait_group 0;" ::: "memory");
    __syncthreads();

    // ldmatrix bases (b16 view: 16 "b16 cols" = 32 int8 per k-step chunk pair).
    // A: row = warp_m*64 + mi*16 + (l&15)
    uint32_t a_base[4], a_s[4];
    {
        int arow_l = l & 15;
#pragma unroll
        for (int mi = 0; mi < 4; ++mi) {
            int row = warp_m * 64 + mi * 16 + arow_l;
            a_base[mi] = Abase + row * 256;
            a_s[mi] = (uint32_t)((row & 7) << 4);
        }
    }
    const uint32_t ac0 = (uint32_t)(l >> 4);
    // B: row = warp_n*32 + j*16 + (l&7) + ((l>>4)<<3)
    uint32_t b_off[2], b_s[2];
    {
        int brow_l = (l & 7) + ((l >> 4) << 3);
#pragma unroll
        for (int j = 0; j < 2; ++j) {
            int row = warp_n * 32 + j * 16 + brow_l;
            b_off[j] = (uint32_t)(row * 256);
            b_s[j] = (uint32_t)((row & 7) << 4);
        }
    }
    const uint32_t bc0 = (uint32_t)((l >> 3) & 1);

    float rowsum[8];
#pragma unroll
    for (int i = 0; i < 8; ++i) rowsum[i] = 0.f;

#pragma unroll 1
    for (int sub = 0; sub < SUBT; ++sub) {
        uint32_t cur = Bb[sub & 1];
        if (sub + 1 < SUBT)
            cp_fill(Bb[(sub + 1) & 1], Bg + (size_t)(sub + 1) * NT * D_DIM, tid);
        asm volatile("cp.async.commit_group;" ::: "memory");

        int acc[4][4][4];
#pragma unroll
        for (int mi = 0; mi < 4; ++mi)
#pragma unroll
            for (int nj = 0; nj < 4; ++nj)
#pragma unroll
                for (int q = 0; q < 4; ++q) acc[mi][nj][q] = 0;

#pragma unroll
        for (int ks = 0; ks < 8; ++ks) {
            uint32_t af[4][4];
#pragma unroll
            for (int mi = 0; mi < 4; ++mi)
                ldsm_x4(af[mi], a_base[mi] + ((((uint32_t)(ks * 2) + ac0) << 4) ^ a_s[mi]));
            uint32_t bf[2][4];
#pragma unroll
            for (int j = 0; j < 2; ++j)
                ldsm_x4(bf[j], cur + b_off[j] + ((((uint32_t)(ks * 2) + bc0) << 4) ^ b_s[j]));
#pragma unroll
            for (int mi = 0; mi < 4; ++mi) {
                mma_s8(acc[mi][0], af[mi], &bf[0][0]);
                mma_s8(acc[mi][1], af[mi], &bf[0][2]);
                mma_s8(acc[mi][2], af[mi], &bf[1][0]);
                mma_s8(acc[mi][3], af[mi], &bf[1][2]);
            }
        }

        // exp epilogue: logit*log2e = acc*QSCALE; shifted by -20*log2e
#pragma unroll
        for (int mi = 0; mi < 4; ++mi) {
            float t0 = 0.f, t1 = 0.f;
#pragma unroll
            for (int nj = 0; nj < 4; ++nj) {
                t0 += ex2f(fmaf((float)acc[mi][nj][0], QSCALE, -LOG2E20));
                t0 += ex2f(fmaf((float)acc[mi][nj][1], QSCALE, -LOG2E20));
                t1 += ex2f(fmaf((float)acc[mi][nj][2], QSCALE, -LOG2E20));
                t1 += ex2f(fmaf((float)acc[mi][nj][3], QSCALE, -LOG2E20));
            }
            rowsum[mi * 2]     += t0;
            rowsum[mi * 2 + 1] += t1;
        }

        asm volatile("cp.async.wait_group 0;" ::: "memory");
        __syncthreads();
    }

    // Lanes l%4 share a row
#pragma unroll
    for (int i = 0; i < 8; ++i) {
        float v = rowsum[i];
        v += __shfl_xor_sync(0xffffffffu, v, 1);
        v += __shfl_xor_sync(0xffffffffu, v, 2);
        rowsum[i] = v;
    }
    if ((l & 3) == 0) {
#pragma unroll
        for (int i = 0; i < 8; ++i) {
            int row = warp_m * 64 + (i >> 1) * 16 + (l >> 2) + (i & 1) * 8;
            wsum[warp_n][row] = rowsum[i];
        }
    }
    __syncthreads();
    if (tid < MT) {
        float v = wsum[0][tid] + wsum[1][tid] + wsum[2][tid] + wsum[3][tid];
        g_ps[blockIdx.y * B_ANCH + aBase + tid] = v;
    }
}

// ---------------------------------------------------------------------------
// Finalize: one launch, 1024 threads, 2 anchors per thread. (shift-20 partials)
// ---------------------------------------------------------------------------
__global__ void __launch_bounds__(1024, 1) finalize_kernel(const int* __restrict__ counts,
                                                           float* __restrict__ out) {
    __shared__ float red[1024];
    int tid = threadIdx.x;
    float local = 0.f;

#pragma unroll
    for (int h = 0; h < 2; ++h) {
        int b = tid + h * 1024;
        float ssum = 0.f;
#pragma unroll
        for (int c = 0; c < NSPLIT; ++c) ssum += g_ps[c * B_ANCH + b];
        float lse = 20.0f + logf(ssum);

        int cnt = counts[b];
        float pv[P_POS];
        float m4 = -INFINITY;
#pragma unroll
        for (int j = 0; j < P_POS; ++j) {
            pv[j] = g_pos[b * P_POS + j];
            m4 = fmaxf(m4, pv[j]);
        }
        float se = 0.f, wp = 0.f, al = 0.f;
#pragma unroll
        for (int j = 0; j < P_POS; ++j) {
            if (j < cnt) al += logaddexpf_(pv[j], lse) - pv[j];
            float e = expf(pv[j] - m4);
            se += e;
            wp += e * pv[j];
        }
        if (cnt > 1) {
            float wps = wp / se;
            al += ALPHA_W * (logaddexpf_(wps, lse) - wps);
        }
        local += al;
    }

    red[tid] = local;
    __syncthreads();
    for (int o = 512; o > 0; o >>= 1) {
        if (tid < o) red[tid] += red[tid + o];
        __syncthreads();
    }
    if (tid == 0) out[0] = red[0] / (float)B_ANCH;
}

// ---------------------------------------------------------------------------
extern "C" void kernel_launch(void* const* d_in, const int* in_sizes, int n_in,
                              void* d_out, int out_size) {
    const float* anc = (const float*)d_in[0];
    const float* pos = (const float*)d_in[1];
    const float* neg = (const float*)d_in[2];
    const int*   cnt = (const int*)d_in[3];
    float* out = (float*)d_out;
    (void)in_sizes; (void)n_in; (void)out_size;

    cudaFuncSetAttribute(neg_mma_kernel,
                         cudaFuncAttributeMaxDynamicSharedMemorySize, SMEM_TOTAL);

    prologue_kernel<<<U_TOT / 8, 256>>>(anc, pos, neg);
    neg_mma_kernel<<<dim3(B_ANCH / MT, NSPLIT), 256, SMEM_TOTAL>>>();
    finalize_kernel<<<1, 1024>>>(cnt, out);
}

// round 15
// speedup vs baseline: 2.3975x; 2.3975x over previous
#include <cuda_runtime.h>
#include <cuda_bf16.h>
#include <stdint.h>
#include <math.h>

// Problem constants
#define B_ANCH 2048
#define P_POS  4
#define D_DIM  256
#define NNEG   32768
#define INV_T  20.0f
#define ALPHA_W 0.1f
#define EPS_N  1e-12f
#define LOG2E20 28.853900817779268f   // 20 * log2(e)

// Tiling: MT=64, NT=64, occupancy 2
#define MT     64
#define NT     64
#define NSPLIT 64
#define CHUNK  (NNEG / NSPLIT)   // 512
#define SUBT   (CHUNK / NT)      // 8
#define NTHR   128
#define TILE_BYTES (MT * D_DIM * 2)      // 32 KB
#define SMEM_TOTAL (3 * TILE_BYTES)      // 96 KB -> 2 CTAs/SM

// ---------------- scratch ----------------
__device__ __align__(16) __nv_bfloat16  g_an_bf[B_ANCH * D_DIM];
__device__ __align__(16) __nv_bfloat16  g_nn_bf[NNEG * D_DIM];
__device__ float g_pos[B_ANCH * P_POS];
__device__ float g_ps[NSPLIT * B_ANCH];

// ---------------- helpers ----------------
__device__ __forceinline__ uint32_t smem_u32(const void* p) {
    uint32_t a;
    asm("{ .reg .u64 t; cvta.to.shared.u64 t, %1; cvt.u32.u64 %0, t; }" : "=r"(a) : "l"(p));
    return a;
}
__device__ __forceinline__ void ldsm_x4(uint32_t* r, uint32_t addr) {
    asm volatile("ldmatrix.sync.aligned.m8n8.x4.shared.b16 {%0,%1,%2,%3}, [%4];"
                 : "=r"(r[0]), "=r"(r[1]), "=r"(r[2]), "=r"(r[3]) : "r"(addr));
}
__device__ __forceinline__ void mma_bf16(float* d, const uint32_t* a, const uint32_t* b) {
    asm volatile("mma.sync.aligned.m16n8k16.row.col.f32.bf16.bf16.f32 "
                 "{%0,%1,%2,%3}, {%4,%5,%6,%7}, {%8,%9}, {%0,%1,%2,%3};"
                 : "+f"(d[0]), "+f"(d[1]), "+f"(d[2]), "+f"(d[3])
                 : "r"(a[0]), "r"(a[1]), "r"(a[2]), "r"(a[3]), "r"(b[0]), "r"(b[1]));
}
__device__ __forceinline__ float ex2f(float x) {
    float y;
    asm("ex2.approx.ftz.f32 %0, %1;" : "=f"(y) : "f"(x));
    return y;
}
__device__ __forceinline__ float logaddexpf_(float a, float b) {
    float hi = fmaxf(a, b), lo = fminf(a, b);
    return hi + log1pf(expf(lo - hi));
}

// 64 rows x 512B tile fill (128 threads). 16B chunks XOR-swizzled: chunk' = chunk ^ (row&7)
__device__ __forceinline__ void cp_fill(uint32_t dstBase, const __nv_bfloat16* src, int tid) {
#pragma unroll
    for (int i = 0; i < 16; ++i) {
        int idx = tid + (i << 7);       // 0..2047
        int r = idx >> 5;               // row 0..63
        int c = idx & 31;               // chunk 0..31
        uint32_t dst = dstBase + r * 512 + (uint32_t)((c ^ (r & 7)) << 4);
        const void* g = (const void*)(src + (size_t)r * D_DIM + c * 8);
        asm volatile("cp.async.cg.shared.global [%0], [%1], 16;" :: "r"(dst), "l"(g) : "memory");
    }
}

// ---------------------------------------------------------------------------
// Fused prologue (warp per unit): anchor-norm / negative-norm / pos_sim
// ---------------------------------------------------------------------------
#define U_ANC  B_ANCH
#define U_NEG  (U_ANC + NNEG)
#define U_TOT  (U_NEG + B_ANCH * P_POS)

__global__ void prologue_kernel(const float* __restrict__ anc,
                                const float* __restrict__ pos,
                                const float* __restrict__ neg) {
    int u = (blockIdx.x * blockDim.x + threadIdx.x) >> 5;
    int lane = threadIdx.x & 31;
    if (u >= U_TOT) return;

    if (u < U_NEG) {
        const float* src;
        __nv_bfloat16* dst;
        if (u < U_ANC) { src = anc + (size_t)u * D_DIM;           dst = g_an_bf + (size_t)u * D_DIM; }
        else           { src = neg + (size_t)(u - U_ANC) * D_DIM; dst = g_nn_bf + (size_t)(u - U_ANC) * D_DIM; }
        const float4* s4 = (const float4*)src;
        float4 v0 = s4[lane];
        float4 v1 = s4[lane + 32];
        float ss = v0.x*v0.x + v0.y*v0.y + v0.z*v0.z + v0.w*v0.w
                 + v1.x*v1.x + v1.y*v1.y + v1.z*v1.z + v1.w*v1.w;
#pragma unroll
        for (int o = 16; o > 0; o >>= 1) ss += __shfl_xor_sync(0xffffffffu, ss, o);
        float inv = 1.0f / fmaxf(sqrtf(ss), EPS_N);
        v0.x *= inv; v0.y *= inv; v0.z *= inv; v0.w *= inv;
        v1.x *= inv; v1.y *= inv; v1.z *= inv; v1.w *= inv;
        __nv_bfloat162* b2 = (__nv_bfloat162*)dst;
        b2[lane * 2]            = __nv_bfloat162(__float2bfloat16_rn(v0.x), __float2bfloat16_rn(v0.y));
        b2[lane * 2 + 1]        = __nv_bfloat162(__float2bfloat16_rn(v0.z), __float2bfloat16_rn(v0.w));
        b2[(lane + 32) * 2]     = __nv_bfloat162(__float2bfloat16_rn(v1.x), __float2bfloat16_rn(v1.y));
        b2[(lane + 32) * 2 + 1] = __nv_bfloat162(__float2bfloat16_rn(v1.z), __float2bfloat16_rn(v1.w));
    } else {
        int p = u - U_NEG;
        int b = p >> 2;
        const float4* psrc = (const float4*)(pos + (size_t)p * D_DIM);
        const float4* asrc = (const float4*)(anc + (size_t)b * D_DIM);
        float sp = 0.f, sa = 0.f, dot = 0.f;
#pragma unroll
        for (int t = 0; t < 2; ++t) {
            float4 pv = psrc[lane + 32 * t];
            float4 av = asrc[lane + 32 * t];
            sp  += pv.x*pv.x + pv.y*pv.y + pv.z*pv.z + pv.w*pv.w;
            sa  += av.x*av.x + av.y*av.y + av.z*av.z + av.w*av.w;
            dot += pv.x*av.x + pv.y*av.y + pv.z*av.z + pv.w*av.w;
        }
#pragma unroll
        for (int o = 16; o > 0; o >>= 1) {
            sp  += __shfl_xor_sync(0xffffffffu, sp, o);
            sa  += __shfl_xor_sync(0xffffffffu, sa, o);
            dot += __shfl_xor_sync(0xffffffffu, dot, o);
        }
        if (lane == 0)
            g_pos[p] = dot / (fmaxf(sqrtf(sp), EPS_N) * fmaxf(sqrtf(sa), EPS_N)) * INV_T;
    }
}

// ---------------------------------------------------------------------------
// Main: bf16 warp-MMA GEMM + exp partial-sum. grid (32, NSPLIT), 128 thr,
// 4 warps (2m x 2n), warp tile 32x32. 2 CTAs/SM for structural overlap.
// ---------------------------------------------------------------------------
__global__ void __launch_bounds__(NTHR, 2) neg_mma_kernel() {
    extern __shared__ char smem[];
    __shared__ float wsum[2][MT];

    const uint32_t Abase = smem_u32(smem);
    const uint32_t Bb[2] = { Abase + TILE_BYTES, Abase + 2 * TILE_BYTES };

    int tid = threadIdx.x;
    int l = tid & 31;
    int wid = tid >> 5;
    int warp_m = wid >> 1;      // 0..1
    int warp_n = wid & 1;       // 0..1
    int aBase = blockIdx.x * MT;
    int nBase = blockIdx.y * CHUNK;

    const __nv_bfloat16* Ag = g_an_bf + (size_t)aBase * D_DIM;
    const __nv_bfloat16* Bg = g_nn_bf + (size_t)nBase * D_DIM;

    cp_fill(Abase, Ag, tid);
    cp_fill(Bb[0], Bg, tid);
    asm volatile("cp.async.commit_group;" ::: "memory");
    asm volatile("cp.async.wait_group 0;" ::: "memory");
    __syncthreads();

    // A: row = warp_m*32 + mi*16 + (l&15), mi 0..1
    uint32_t a_base[2], a_s[2];
    {
        int arow_l = l & 15;
#pragma unroll
        for (int mi = 0; mi < 2; ++mi) {
            int row = warp_m * 32 + mi * 16 + arow_l;
            a_base[mi] = Abase + row * 512;
            a_s[mi] = (uint32_t)((row & 7) << 4);
        }
    }
    const uint32_t ac0 = (uint32_t)(l >> 4);
    // B: row = warp_n*32 + j*16 + (l&7) + ((l>>4)<<3), j 0..1
    uint32_t b_off[2], b_s[2];
    {
        int brow_l = (l & 7) + ((l >> 4) << 3);
#pragma unroll
        for (int j = 0; j < 2; ++j) {
            int row = warp_n * 32 + j * 16 + brow_l;
            b_off[j] = (uint32_t)(row * 512);
            b_s[j] = (uint32_t)((row & 7) << 4);
        }
    }
    const uint32_t bc0 = (uint32_t)((l >> 3) & 1);

    float rowsum[4] = {0.f, 0.f, 0.f, 0.f};

#pragma unroll 1
    for (int sub = 0; sub < SUBT; ++sub) {
        uint32_t cur = Bb[sub & 1];
        if (sub + 1 < SUBT)
            cp_fill(Bb[(sub + 1) & 1], Bg + (size_t)(sub + 1) * NT * D_DIM, tid);
        asm volatile("cp.async.commit_group;" ::: "memory");

        float acc[2][4][4];
#pragma unroll
        for (int mi = 0; mi < 2; ++mi)
#pragma unroll
            for (int nj = 0; nj < 4; ++nj)
#pragma unroll
                for (int q = 0; q < 4; ++q) acc[mi][nj][q] = 0.f;

#pragma unroll
        for (int ks = 0; ks < 16; ++ks) {
            uint32_t af[2][4];
#pragma unroll
            for (int mi = 0; mi < 2; ++mi)
                ldsm_x4(af[mi], a_base[mi] + ((((uint32_t)(ks * 2) + ac0) << 4) ^ a_s[mi]));
            uint32_t bf[2][4];
#pragma unroll
            for (int j = 0; j < 2; ++j)
                ldsm_x4(bf[j], cur + b_off[j] + ((((uint32_t)(ks * 2) + bc0) << 4) ^ b_s[j]));
#pragma unroll
            for (int mi = 0; mi < 2; ++mi) {
                mma_bf16(acc[mi][0], af[mi], &bf[0][0]);
                mma_bf16(acc[mi][1], af[mi], &bf[0][2]);
                mma_bf16(acc[mi][2], af[mi], &bf[1][0]);
                mma_bf16(acc[mi][3], af[mi], &bf[1][2]);
            }
        }

        // exp epilogue
#pragma unroll
        for (int mi = 0; mi < 2; ++mi) {
            float t0 = 0.f, t1 = 0.f;
#pragma unroll
            for (int nj = 0; nj < 4; ++nj) {
                t0 += ex2f(fmaf(acc[mi][nj][0], LOG2E20, -LOG2E20));
                t0 += ex2f(fmaf(acc[mi][nj][1], LOG2E20, -LOG2E20));
                t1 += ex2f(fmaf(acc[mi][nj][2], LOG2E20, -LOG2E20));
                t1 += ex2f(fmaf(acc[mi][nj][3], LOG2E20, -LOG2E20));
            }
            rowsum[mi * 2]     += t0;
            rowsum[mi * 2 + 1] += t1;
        }

        asm volatile("cp.async.wait_group 0;" ::: "memory");
        __syncthreads();
    }

    // Lanes l%4 share a row
#pragma unroll
    for (int i = 0; i < 4; ++i) {
        float v = rowsum[i];
        v += __shfl_xor_sync(0xffffffffu, v, 1);
        v += __shfl_xor_sync(0xffffffffu, v, 2);
        rowsum[i] = v;
    }
    if ((l & 3) == 0) {
#pragma unroll
        for (int i = 0; i < 4; ++i) {
            int row = warp_m * 32 + (i >> 1) * 16 + (l >> 2) + (i & 1) * 8;
            wsum[warp_n][row] = rowsum[i];
        }
    }
    __syncthreads();
    if (tid < MT) {
        float v = wsum[0][tid] + wsum[1][tid];
        g_ps[blockIdx.y * B_ANCH + aBase + tid] = v;
    }
}

// ---------------------------------------------------------------------------
// Finalize: one launch, 1024 threads, 2 anchors per thread (shift-20 partials)
// ---------------------------------------------------------------------------
__global__ void __launch_bounds__(1024, 1) finalize_kernel(const int* __restrict__ counts,
                                                           float* __restrict__ out) {
    __shared__ float red[1024];
    int tid = threadIdx.x;
    float local = 0.f;

#pragma unroll
    for (int h = 0; h < 2; ++h) {
        int b = tid + h * 1024;
        float ssum = 0.f;
#pragma unroll
        for (int c = 0; c < NSPLIT; ++c) ssum += g_ps[c * B_ANCH + b];
        float lse = 20.0f + logf(ssum);

        int cnt = counts[b];
        float pv[P_POS];
        float m4 = -INFINITY;
#pragma unroll
        for (int j = 0; j < P_POS; ++j) {
            pv[j] = g_pos[b * P_POS + j];
            m4 = fmaxf(m4, pv[j]);
        }
        float se = 0.f, wp = 0.f, al = 0.f;
#pragma unroll
        for (int j = 0; j < P_POS; ++j) {
            if (j < cnt) al += logaddexpf_(pv[j], lse) - pv[j];
            float e = expf(pv[j] - m4);
            se += e;
            wp += e * pv[j];
        }
        if (cnt > 1) {
            float wps = wp / se;
            al += ALPHA_W * (logaddexpf_(wps, lse) - wps);
        }
        local += al;
    }

    red[tid] = local;
    __syncthreads();
    for (int o = 512; o > 0; o >>= 1) {
        if (tid < o) red[tid] += red[tid + o];
        __syncthreads();
    }
    if (tid == 0) out[0] = red[0] / (float)B_ANCH;
}

// ---------------------------------------------------------------------------
extern "C" void kernel_launch(void* const* d_in, const int* in_sizes, int n_in,
                              void* d_out, int out_size) {
    const float* anc = (const float*)d_in[0];
    const float* pos = (const float*)d_in[1];
    const float* neg = (const float*)d_in[2];
    const int*   cnt = (const int*)d_in[3];
    float* out = (float*)d_out;
    (void)in_sizes; (void)n_in; (void)out_size;

    cudaFuncSetAttribute(neg_mma_kernel,
                         cudaFuncAttributeMaxDynamicSharedMemorySize, SMEM_TOTAL);

    prologue_kernel<<<U_TOT / 8, 256>>>(anc, pos, neg);
    neg_mma_kernel<<<dim3(B_ANCH / MT, NSPLIT), NTHR, SMEM_TOTAL>>>();
    finalize_kernel<<<1, 1024>>>(cnt, out);
}

// round 16
// speedup vs baseline: 2.4455x; 1.0200x over previous
#include <cuda_runtime.h>
#include <cuda_bf16.h>
#include <stdint.h>
#include <math.h>

// Problem constants
#define B_ANCH 2048
#define P_POS  4
#define D_DIM  256
#define NNEG   32768
#define INV_T  20.0f
#define ALPHA_W 0.1f
#define EPS_N  1e-12f
#define LOG2E20 28.853900817779268f   // 20 * log2(e)

// Tiling: MT=64, NT=64, occupancy 2, A register-resident
#define MT     64
#define NT     64
#define NSPLIT 64
#define CHUNK  (NNEG / NSPLIT)   // 512
#define SUBT   (CHUNK / NT)      // 8
#define NTHR   128
#define TILE_BYTES (MT * D_DIM * 2)      // 32 KB
#define SMEM_TOTAL (3 * TILE_BYTES)      // 96 KB -> 2 CTAs/SM

// ---------------- scratch ----------------
__device__ __align__(16) __nv_bfloat16  g_an_bf[B_ANCH * D_DIM];
__device__ __align__(16) __nv_bfloat16  g_nn_bf[NNEG * D_DIM];
__device__ float g_pos[B_ANCH * P_POS];
__device__ float g_ps[NSPLIT * B_ANCH];

// ---------------- helpers ----------------
__device__ __forceinline__ uint32_t smem_u32(const void* p) {
    uint32_t a;
    asm("{ .reg .u64 t; cvta.to.shared.u64 t, %1; cvt.u32.u64 %0, t; }" : "=r"(a) : "l"(p));
    return a;
}
__device__ __forceinline__ void ldsm_x4(uint32_t* r, uint32_t addr) {
    asm volatile("ldmatrix.sync.aligned.m8n8.x4.shared.b16 {%0,%1,%2,%3}, [%4];"
                 : "=r"(r[0]), "=r"(r[1]), "=r"(r[2]), "=r"(r[3]) : "r"(addr));
}
__device__ __forceinline__ void mma_bf16(float* d, const uint32_t* a, const uint32_t* b) {
    asm volatile("mma.sync.aligned.m16n8k16.row.col.f32.bf16.bf16.f32 "
                 "{%0,%1,%2,%3}, {%4,%5,%6,%7}, {%8,%9}, {%0,%1,%2,%3};"
                 : "+f"(d[0]), "+f"(d[1]), "+f"(d[2]), "+f"(d[3])
                 : "r"(a[0]), "r"(a[1]), "r"(a[2]), "r"(a[3]), "r"(b[0]), "r"(b[1]));
}
__device__ __forceinline__ float ex2f(float x) {
    float y;
    asm("ex2.approx.ftz.f32 %0, %1;" : "=f"(y) : "f"(x));
    return y;
}
__device__ __forceinline__ float logaddexpf_(float a, float b) {
    float hi = fmaxf(a, b), lo = fminf(a, b);
    return hi + log1pf(expf(lo - hi));
}

// 64 rows x 512B tile fill (128 threads). 16B chunks XOR-swizzled: chunk' = chunk ^ (row&7)
__device__ __forceinline__ void cp_fill(uint32_t dstBase, const __nv_bfloat16* src, int tid) {
#pragma unroll
    for (int i = 0; i < 16; ++i) {
        int idx = tid + (i << 7);       // 0..2047
        int r = idx >> 5;               // row 0..63
        int c = idx & 31;               // chunk 0..31
        uint32_t dst = dstBase + r * 512 + (uint32_t)((c ^ (r & 7)) << 4);
        const void* g = (const void*)(src + (size_t)r * D_DIM + c * 8);
        asm volatile("cp.async.cg.shared.global [%0], [%1], 16;" :: "r"(dst), "l"(g) : "memory");
    }
}

// ---------------------------------------------------------------------------
// Fused prologue (warp per unit): anchor-norm / negative-norm / pos_sim
// ---------------------------------------------------------------------------
#define U_ANC  B_ANCH
#define U_NEG  (U_ANC + NNEG)
#define U_TOT  (U_NEG + B_ANCH * P_POS)

__global__ void prologue_kernel(const float* __restrict__ anc,
                                const float* __restrict__ pos,
                                const float* __restrict__ neg) {
    int u = (blockIdx.x * blockDim.x + threadIdx.x) >> 5;
    int lane = threadIdx.x & 31;
    if (u >= U_TOT) return;

    if (u < U_NEG) {
        const float* src;
        __nv_bfloat16* dst;
        if (u < U_ANC) { src = anc + (size_t)u * D_DIM;           dst = g_an_bf + (size_t)u * D_DIM; }
        else           { src = neg + (size_t)(u - U_ANC) * D_DIM; dst = g_nn_bf + (size_t)(u - U_ANC) * D_DIM; }
        const float4* s4 = (const float4*)src;
        float4 v0 = s4[lane];
        float4 v1 = s4[lane + 32];
        float ss = v0.x*v0.x + v0.y*v0.y + v0.z*v0.z + v0.w*v0.w
                 + v1.x*v1.x + v1.y*v1.y + v1.z*v1.z + v1.w*v1.w;
#pragma unroll
        for (int o = 16; o > 0; o >>= 1) ss += __shfl_xor_sync(0xffffffffu, ss, o);
        float inv = 1.0f / fmaxf(sqrtf(ss), EPS_N);
        v0.x *= inv; v0.y *= inv; v0.z *= inv; v0.w *= inv;
        v1.x *= inv; v1.y *= inv; v1.z *= inv; v1.w *= inv;
        __nv_bfloat162* b2 = (__nv_bfloat162*)dst;
        b2[lane * 2]            = __nv_bfloat162(__float2bfloat16_rn(v0.x), __float2bfloat16_rn(v0.y));
        b2[lane * 2 + 1]        = __nv_bfloat162(__float2bfloat16_rn(v0.z), __float2bfloat16_rn(v0.w));
        b2[(lane + 32) * 2]     = __nv_bfloat162(__float2bfloat16_rn(v1.x), __float2bfloat16_rn(v1.y));
        b2[(lane + 32) * 2 + 1] = __nv_bfloat162(__float2bfloat16_rn(v1.z), __float2bfloat16_rn(v1.w));
    } else {
        int p = u - U_NEG;
        int b = p >> 2;
        const float4* psrc = (const float4*)(pos + (size_t)p * D_DIM);
        const float4* asrc = (const float4*)(anc + (size_t)b * D_DIM);
        float sp = 0.f, sa = 0.f, dot = 0.f;
#pragma unroll
        for (int t = 0; t < 2; ++t) {
            float4 pv = psrc[lane + 32 * t];
            float4 av = asrc[lane + 32 * t];
            sp  += pv.x*pv.x + pv.y*pv.y + pv.z*pv.z + pv.w*pv.w;
            sa  += av.x*av.x + av.y*av.y + av.z*av.z + av.w*av.w;
            dot += pv.x*av.x + pv.y*av.y + pv.z*av.z + pv.w*av.w;
        }
#pragma unroll
        for (int o = 16; o > 0; o >>= 1) {
            sp  += __shfl_xor_sync(0xffffffffu, sp, o);
            sa  += __shfl_xor_sync(0xffffffffu, sa, o);
            dot += __shfl_xor_sync(0xffffffffu, dot, o);
        }
        if (lane == 0)
            g_pos[p] = dot / (fmaxf(sqrtf(sp), EPS_N) * fmaxf(sqrtf(sa), EPS_N)) * INV_T;
    }
}

// ---------------------------------------------------------------------------
// Main: bf16 warp-MMA GEMM, A register-resident. grid (32, NSPLIT), 128 thr,
// 4 warps (2m x 2n), warp tile 32x32, 2 CTAs/SM.
// ---------------------------------------------------------------------------
__global__ void __launch_bounds__(NTHR, 2) neg_mma_kernel() {
    extern __shared__ char smem[];
    __shared__ float wsum[2][MT];

    const uint32_t Abase = smem_u32(smem);
    const uint32_t Bb[2] = { Abase + TILE_BYTES, Abase + 2 * TILE_BYTES };

    int tid = threadIdx.x;
    int l = tid & 31;
    int wid = tid >> 5;
    int warp_m = wid >> 1;      // 0..1
    int warp_n = wid & 1;       // 0..1
    int aBase = blockIdx.x * MT;
    int nBase = blockIdx.y * CHUNK;

    const __nv_bfloat16* Ag = g_an_bf + (size_t)aBase * D_DIM;
    const __nv_bfloat16* Bg = g_nn_bf + (size_t)nBase * D_DIM;

    cp_fill(Abase, Ag, tid);
    cp_fill(Bb[0], Bg, tid);
    asm volatile("cp.async.commit_group;" ::: "memory");
    asm volatile("cp.async.wait_group 0;" ::: "memory");
    __syncthreads();

    // A ldmatrix bases: row = warp_m*32 + mi*16 + (l&15), mi 0..1
    uint32_t a_base[2], a_s[2];
    {
        int arow_l = l & 15;
#pragma unroll
        for (int mi = 0; mi < 2; ++mi) {
            int row = warp_m * 32 + mi * 16 + arow_l;
            a_base[mi] = Abase + row * 512;
            a_s[mi] = (uint32_t)((row & 7) << 4);
        }
    }
    const uint32_t ac0 = (uint32_t)(l >> 4);

    // Load ALL A fragments into registers once (invariant across subtiles).
    uint32_t afr[2][16][4];   // 128 regs
#pragma unroll
    for (int ks = 0; ks < 16; ++ks)
#pragma unroll
        for (int mi = 0; mi < 2; ++mi)
            ldsm_x4(afr[mi][ks], a_base[mi] + ((((uint32_t)(ks * 2) + ac0) << 4) ^ a_s[mi]));

    // B: row = warp_n*32 + j*16 + (l&7) + ((l>>4)<<3), j 0..1
    uint32_t b_off[2], b_s[2];
    {
        int brow_l = (l & 7) + ((l >> 4) << 3);
#pragma unroll
        for (int j = 0; j < 2; ++j) {
            int row = warp_n * 32 + j * 16 + brow_l;
            b_off[j] = (uint32_t)(row * 512);
            b_s[j] = (uint32_t)((row & 7) << 4);
        }
    }
    const uint32_t bc0 = (uint32_t)((l >> 3) & 1);

    float rowsum[4] = {0.f, 0.f, 0.f, 0.f};

#pragma unroll 1
    for (int sub = 0; sub < SUBT; ++sub) {
        uint32_t cur = Bb[sub & 1];
        if (sub + 1 < SUBT)
            cp_fill(Bb[(sub + 1) & 1], Bg + (size_t)(sub + 1) * NT * D_DIM, tid);
        asm volatile("cp.async.commit_group;" ::: "memory");

        float acc[2][4][4];
#pragma unroll
        for (int mi = 0; mi < 2; ++mi)
#pragma unroll
            for (int nj = 0; nj < 4; ++nj)
#pragma unroll
                for (int q = 0; q < 4; ++q) acc[mi][nj][q] = 0.f;

#pragma unroll
        for (int ks = 0; ks < 16; ++ks) {
            uint32_t bf[2][4];
#pragma unroll
            for (int j = 0; j < 2; ++j)
                ldsm_x4(bf[j], cur + b_off[j] + ((((uint32_t)(ks * 2) + bc0) << 4) ^ b_s[j]));
#pragma unroll
            for (int mi = 0; mi < 2; ++mi) {
                mma_bf16(acc[mi][0], afr[mi][ks], &bf[0][0]);
                mma_bf16(acc[mi][1], afr[mi][ks], &bf[0][2]);
                mma_bf16(acc[mi][2], afr[mi][ks], &bf[1][0]);
                mma_bf16(acc[mi][3], afr[mi][ks], &bf[1][2]);
            }
        }

        // exp epilogue
#pragma unroll
        for (int mi = 0; mi < 2; ++mi) {
            float t0 = 0.f, t1 = 0.f;
#pragma unroll
            for (int nj = 0; nj < 4; ++nj) {
                t0 += ex2f(fmaf(acc[mi][nj][0], LOG2E20, -LOG2E20));
                t0 += ex2f(fmaf(acc[mi][nj][1], LOG2E20, -LOG2E20));
                t1 += ex2f(fmaf(acc[mi][nj][2], LOG2E20, -LOG2E20));
                t1 += ex2f(fmaf(acc[mi][nj][3], LOG2E20, -LOG2E20));
            }
            rowsum[mi * 2]     += t0;
            rowsum[mi * 2 + 1] += t1;
        }

        asm volatile("cp.async.wait_group 0;" ::: "memory");
        __syncthreads();
    }

    // Lanes l%4 share a row
#pragma unroll
    for (int i = 0; i < 4; ++i) {
        float v = rowsum[i];
        v += __shfl_xor_sync(0xffffffffu, v, 1);
        v += __shfl_xor_sync(0xffffffffu, v, 2);
        rowsum[i] = v;
    }
    if ((l & 3) == 0) {
#pragma unroll
        for (int i = 0; i < 4; ++i) {
            int row = warp_m * 32 + (i >> 1) * 16 + (l >> 2) + (i & 1) * 8;
            wsum[warp_n][row] = rowsum[i];
        }
    }
    __syncthreads();
    if (tid < MT) {
        float v = wsum[0][tid] + wsum[1][tid];
        g_ps[blockIdx.y * B_ANCH + aBase + tid] = v;
    }
}

// ---------------------------------------------------------------------------
// Finalize: one launch, 1024 threads, 2 anchors per thread (shift-20 partials)
// ---------------------------------------------------------------------------
__global__ void __launch_bounds__(1024, 1) finalize_kernel(const int* __restrict__ counts,
                                                           float* __restrict__ out) {
    __shared__ float red[1024];
    int tid = threadIdx.x;
    float local = 0.f;

#pragma unroll
    for (int h = 0; h < 2; ++h) {
        int b = tid + h * 1024;
        float ssum = 0.f;
#pragma unroll
        for (int c = 0; c < NSPLIT; ++c) ssum += g_ps[c * B_ANCH + b];
        float lse = 20.0f + logf(ssum);

        int cnt = counts[b];
        float pv[P_POS];
        float m4 = -INFINITY;
#pragma unroll
        for (int j = 0; j < P_POS; ++j) {
            pv[j] = g_pos[b * P_POS + j];
            m4 = fmaxf(m4, pv[j]);
        }
        float se = 0.f, wp = 0.f, al = 0.f;
#pragma unroll
        for (int j = 0; j < P_POS; ++j) {
            if (j < cnt) al += logaddexpf_(pv[j], lse) - pv[j];
            float e = expf(pv[j] - m4);
            se += e;
            wp += e * pv[j];
        }
        if (cnt > 1) {
            float wps = wp / se;
            al += ALPHA_W * (logaddexpf_(wps, lse) - wps);
        }
        local += al;
    }

    red[tid] = local;
    __syncthreads();
    for (int o = 512; o > 0; o >>= 1) {
        if (tid < o) red[tid] += red[tid + o];
        __syncthreads();
    }
    if (tid == 0) out[0] = red[0] / (float)B_ANCH;
}

// ---------------------------------------------------------------------------
extern "C" void kernel_launch(void* const* d_in, const int* in_sizes, int n_in,
                              void* d_out, int out_size) {
    const float* anc = (const float*)d_in[0];
    const float* pos = (const float*)d_in[1];
    const float* neg = (const float*)d_in[2];
    const int*   cnt = (const int*)d_in[3];
    float* out = (float*)d_out;
    (void)in_sizes; (void)n_in; (void)out_size;

    cudaFuncSetAttribute(neg_mma_kernel,
                         cudaFuncAttributeMaxDynamicSharedMemorySize, SMEM_TOTAL);

    prologue_kernel<<<U_TOT / 8, 256>>>(anc, pos, neg);
    neg_mma_kernel<<<dim3(B_ANCH / MT, NSPLIT), NTHR, SMEM_TOTAL>>>();
    finalize_kernel<<<1, 1024>>>(cnt, out);
}